// round 3
// baseline (speedup 1.0000x reference)
#include <cuda_runtime.h>
#include <cuda_bf16.h>
#include <stdint.h>

// Problem dimensions (fixed by the dataset).
#define NNODE 1000000
#define NEDGE 8000000

// Scratch in __device__ globals (no allocation allowed).
__device__ float  g_deg [NNODE];   // in-degree at dst (excl. self-loop)
__device__ float  g_dinv[NNODE];   // rsqrt(deg + 1)
__device__ float4 g_xs  [NNODE];   // x * dinv
__device__ float4 g_acc1[NNODE];   // layer-1 aggregation accumulator
__device__ float2 g_gs  [NNODE];   // (relu(A1 x W1 + b1) W2) * dinv
__device__ float2 g_acc2[NNODE];   // layer-2 aggregation accumulator

// ---------------------------------------------------------------------------
// 1. zero accumulators / degree
__global__ void k_zero(int n) {
    int i = blockIdx.x * blockDim.x + threadIdx.x;
    if (i < n) {
        g_deg [i] = 0.0f;
        g_acc1[i] = make_float4(0.f, 0.f, 0.f, 0.f);
        g_acc2[i] = make_float2(0.f, 0.f);
    }
}

// ---------------------------------------------------------------------------
// 2. in-degree at dst
__global__ void k_deg(const int* __restrict__ dst, int e) {
    int i = blockIdx.x * blockDim.x + threadIdx.x;
    if (i < e) {
        atomicAdd(&g_deg[dst[i]], 1.0f);   // no return use -> RED.F32
    }
}

// ---------------------------------------------------------------------------
// 3. dinv + pre-scaled node features
__global__ void k_prep(const float4* __restrict__ x, int n) {
    int i = blockIdx.x * blockDim.x + threadIdx.x;
    if (i < n) {
        float di = rsqrtf(g_deg[i] + 1.0f);   // self-loop -> deg >= 1
        g_dinv[i] = di;
        float4 v = x[i];
        v.x *= di; v.y *= di; v.z *= di; v.w *= di;
        g_xs[i] = v;
    }
}

// ---------------------------------------------------------------------------
// 4. layer-1 scatter in 4-dim feature space: acc1[dst] += xs[src]
__global__ void k_scatter1(const int* __restrict__ src,
                           const int* __restrict__ dst, int e) {
    int i = blockIdx.x * blockDim.x + threadIdx.x;
    if (i < e) {
        int s = src[i];
        int d = dst[i];
        float4 v = g_xs[s];
        float4* p = &g_acc1[d];
#if __CUDA_ARCH__ >= 900
        asm volatile("red.global.add.v4.f32 [%0], {%1,%2,%3,%4};"
                     :: "l"(p), "f"(v.x), "f"(v.y), "f"(v.z), "f"(v.w)
                     : "memory");
#else
        atomicAdd(&p->x, v.x); atomicAdd(&p->y, v.y);
        atomicAdd(&p->z, v.z); atomicAdd(&p->w, v.w);
#endif
    }
}

// ---------------------------------------------------------------------------
// 5. fused node transform:
//    a4  = dinv * (acc1 + xs)          (= A_norm x incl. self-loop)
//    h64 = relu(a4 @ W1 + b1)          (never materialized)
//    g2  = h64 @ W2
//    gs  = g2 * dinv                   (pre-scale for layer-2 scatter)
__global__ void k_mid(const float* __restrict__ W1,   // [4,64] row-major
                      const float* __restrict__ b1,   // [64]
                      const float* __restrict__ W2,   // [64,2] row-major
                      int n) {
    __shared__ float sW1[256];
    __shared__ float sb1[64];
    __shared__ float sW2[128];
    int t = threadIdx.x;
    if (t < 256) sW1[t] = W1[t];
    if (t < 64)  sb1[t] = b1[t];
    if (t < 128) sW2[t] = W2[t];
    __syncthreads();

    int i = blockIdx.x * blockDim.x + t;
    if (i >= n) return;

    float di = g_dinv[i];
    float4 a  = g_acc1[i];
    float4 xs = g_xs[i];
    float a0 = di * (a.x + xs.x);
    float a1 = di * (a.y + xs.y);
    float a2 = di * (a.z + xs.z);
    float a3 = di * (a.w + xs.w);

    float o0 = 0.f, o1 = 0.f;
#pragma unroll
    for (int j = 0; j < 64; j++) {
        float h = sb1[j];
        h = fmaf(a0, sW1[j],       h);
        h = fmaf(a1, sW1[64 + j],  h);
        h = fmaf(a2, sW1[128 + j], h);
        h = fmaf(a3, sW1[192 + j], h);
        h = fmaxf(h, 0.f);
        o0 = fmaf(h, sW2[2 * j],     o0);
        o1 = fmaf(h, sW2[2 * j + 1], o1);
    }
    g_gs[i] = make_float2(o0 * di, o1 * di);
}

// ---------------------------------------------------------------------------
// 6. layer-2 scatter in 2-dim space: acc2[dst] += gs[src]
__global__ void k_scatter2(const int* __restrict__ src,
                           const int* __restrict__ dst, int e) {
    int i = blockIdx.x * blockDim.x + threadIdx.x;
    if (i < e) {
        int s = src[i];
        int d = dst[i];
        float2 v = g_gs[s];
        float2* p = &g_acc2[d];
#if __CUDA_ARCH__ >= 900
        asm volatile("red.global.add.v2.f32 [%0], {%1,%2};"
                     :: "l"(p), "f"(v.x), "f"(v.y)
                     : "memory");
#else
        atomicAdd(&p->x, v.x); atomicAdd(&p->y, v.y);
#endif
    }
}

// ---------------------------------------------------------------------------
// 7. final: out = dinv * (acc2 + gs) + b2
__global__ void k_final(const float* __restrict__ b2, float2* __restrict__ out, int n) {
    int i = blockIdx.x * blockDim.x + threadIdx.x;
    if (i < n) {
        float di = g_dinv[i];
        float2 a = g_acc2[i];
        float2 g = g_gs[i];
        float bx = __ldg(&b2[0]);
        float by = __ldg(&b2[1]);
        out[i] = make_float2(di * (a.x + g.x) + bx,
                             di * (a.y + g.y) + by);
    }
}

// ---------------------------------------------------------------------------
extern "C" void kernel_launch(void* const* d_in, const int* in_sizes, int n_in,
                              void* d_out, int out_size) {
    const float* x  = (const float*)d_in[0];   // [N,4]
    const int*   ei = (const int*)d_in[1];     // [2,E]  (int32! JAX x64 disabled)
    const float* W1 = (const float*)d_in[2];   // [4,64]
    const float* b1 = (const float*)d_in[3];   // [64]
    const float* W2 = (const float*)d_in[4];   // [64,2]
    const float* b2 = (const float*)d_in[5];   // [2]
    float2*      out = (float2*)d_out;         // [N,2]

    const int n = in_sizes[0] / 4;
    const int e = in_sizes[1] / 2;
    const int* src = ei;
    const int* dst = ei + e;

    const int T = 256;
    const int gn = (n + T - 1) / T;
    const int ge = (e + T - 1) / T;

    k_zero    <<<gn, T>>>(n);
    k_deg     <<<ge, T>>>(dst, e);
    k_prep    <<<gn, T>>>((const float4*)x, n);
    k_scatter1<<<ge, T>>>(src, dst, e);
    k_mid     <<<gn, T>>>(W1, b1, W2, n);
    k_scatter2<<<ge, T>>>(src, dst, e);
    k_final   <<<gn, T>>>(b2, out, n);
}

// round 4
// speedup vs baseline: 1.0162x; 1.0162x over previous
#include <cuda_runtime.h>
#include <cuda_bf16.h>
#include <stdint.h>

#define NNODE 1000000
#define NEDGE 8000000

// Scratch in __device__ globals (no allocation allowed).
__device__ float  g_deg [NNODE];   // in-degree at dst (excl. self-loop)
__device__ float  g_dinv[NNODE];   // rsqrt(deg + 1)
__device__ float4 g_xs  [NNODE];   // x * dinv
__device__ float4 g_acc1[NNODE];   // layer-1 aggregation accumulator
__device__ float2 g_gs  [NNODE];   // (relu(A1 x W1 + b1) W2) * dinv
__device__ float2 g_acc2[NNODE];   // layer-2 aggregation accumulator

// ---------------------------------------------------------------------------
// 1. zero accumulators / degree (vectorized float4 stores)
__global__ void k_zero(int n) {
    int i = blockIdx.x * blockDim.x + threadIdx.x;
    if (i < n) {
        g_deg [i] = 0.0f;
        g_acc1[i] = make_float4(0.f, 0.f, 0.f, 0.f);
        g_acc2[i] = make_float2(0.f, 0.f);
    }
}

// ---------------------------------------------------------------------------
// 2. in-degree at dst — 8 edges/thread, int4 index loads for MLP
__global__ void k_deg(const int* __restrict__ dst, int e) {
    int base = (blockIdx.x * blockDim.x + threadIdx.x) * 8;
    if (base + 8 <= e) {
        int4 d0 = *(const int4*)(dst + base);
        int4 d1 = *(const int4*)(dst + base + 4);
        atomicAdd(&g_deg[d0.x], 1.0f);
        atomicAdd(&g_deg[d0.y], 1.0f);
        atomicAdd(&g_deg[d0.z], 1.0f);
        atomicAdd(&g_deg[d0.w], 1.0f);
        atomicAdd(&g_deg[d1.x], 1.0f);
        atomicAdd(&g_deg[d1.y], 1.0f);
        atomicAdd(&g_deg[d1.z], 1.0f);
        atomicAdd(&g_deg[d1.w], 1.0f);
    } else {
        for (int i = base; i < e; i++) atomicAdd(&g_deg[dst[i]], 1.0f);
    }
}

// ---------------------------------------------------------------------------
// 3. dinv + pre-scaled node features
__global__ void k_prep(const float4* __restrict__ x, int n) {
    int i = blockIdx.x * blockDim.x + threadIdx.x;
    if (i < n) {
        float di = rsqrtf(g_deg[i] + 1.0f);   // self-loop -> deg >= 1
        g_dinv[i] = di;
        float4 v = x[i];
        v.x *= di; v.y *= di; v.z *= di; v.w *= di;
        g_xs[i] = v;
    }
}

// ---------------------------------------------------------------------------
// helpers
__device__ __forceinline__ void red_v4(float4* p, float4 v) {
    asm volatile("red.global.add.v4.f32 [%0], {%1,%2,%3,%4};"
                 :: "l"(p), "f"(v.x), "f"(v.y), "f"(v.z), "f"(v.w) : "memory");
}
__device__ __forceinline__ void red_v2(float2* p, float2 v) {
    asm volatile("red.global.add.v2.f32 [%0], {%1,%2};"
                 :: "l"(p), "f"(v.x), "f"(v.y) : "memory");
}

// ---------------------------------------------------------------------------
// 4. layer-1 scatter: acc1[dst] += xs[src]  — 4 edges/thread, batched gathers
__global__ void k_scatter1(const int* __restrict__ src,
                           const int* __restrict__ dst, int e) {
    int base = (blockIdx.x * blockDim.x + threadIdx.x) * 4;
    if (base + 4 <= e) {
        int4 s = *(const int4*)(src + base);
        int4 d = *(const int4*)(dst + base);
        // issue all gathers first (MLP), then all REDs
        float4 v0 = g_xs[s.x];
        float4 v1 = g_xs[s.y];
        float4 v2 = g_xs[s.z];
        float4 v3 = g_xs[s.w];
        red_v4(&g_acc1[d.x], v0);
        red_v4(&g_acc1[d.y], v1);
        red_v4(&g_acc1[d.z], v2);
        red_v4(&g_acc1[d.w], v3);
    } else {
        for (int i = base; i < e; i++)
            red_v4(&g_acc1[dst[i]], g_xs[src[i]]);
    }
}

// ---------------------------------------------------------------------------
// 5. fused node transform:
//    a4  = dinv * (acc1 + xs)          (= A_norm x incl. self-loop)
//    h64 = relu(a4 @ W1 + b1)          (never materialized)
//    gs  = (h64 @ W2) * dinv           (pre-scaled for layer-2 scatter)
__global__ void k_mid(const float* __restrict__ W1,   // [4,64] row-major
                      const float* __restrict__ b1,   // [64]
                      const float* __restrict__ W2,   // [64,2] row-major
                      int n) {
    __shared__ float sW1[256];
    __shared__ float sb1[64];
    __shared__ float sW2[128];
    int t = threadIdx.x;
    if (t < 256) sW1[t] = W1[t];
    if (t < 64)  sb1[t] = b1[t];
    if (t < 128) sW2[t] = W2[t];
    __syncthreads();

    int i = blockIdx.x * blockDim.x + t;
    if (i >= n) return;

    float di = g_dinv[i];
    float4 a  = g_acc1[i];
    float4 xs = g_xs[i];
    float a0 = di * (a.x + xs.x);
    float a1 = di * (a.y + xs.y);
    float a2 = di * (a.z + xs.z);
    float a3 = di * (a.w + xs.w);

    float o0 = 0.f, o1 = 0.f;
#pragma unroll
    for (int j = 0; j < 64; j++) {
        float h = sb1[j];
        h = fmaf(a0, sW1[j],       h);
        h = fmaf(a1, sW1[64 + j],  h);
        h = fmaf(a2, sW1[128 + j], h);
        h = fmaf(a3, sW1[192 + j], h);
        h = fmaxf(h, 0.f);
        o0 = fmaf(h, sW2[2 * j],     o0);
        o1 = fmaf(h, sW2[2 * j + 1], o1);
    }
    g_gs[i] = make_float2(o0 * di, o1 * di);
}

// ---------------------------------------------------------------------------
// 6. layer-2 scatter: acc2[dst] += gs[src]  — 4 edges/thread
__global__ void k_scatter2(const int* __restrict__ src,
                           const int* __restrict__ dst, int e) {
    int base = (blockIdx.x * blockDim.x + threadIdx.x) * 4;
    if (base + 4 <= e) {
        int4 s = *(const int4*)(src + base);
        int4 d = *(const int4*)(dst + base);
        float2 v0 = g_gs[s.x];
        float2 v1 = g_gs[s.y];
        float2 v2 = g_gs[s.z];
        float2 v3 = g_gs[s.w];
        red_v2(&g_acc2[d.x], v0);
        red_v2(&g_acc2[d.y], v1);
        red_v2(&g_acc2[d.z], v2);
        red_v2(&g_acc2[d.w], v3);
    } else {
        for (int i = base; i < e; i++)
            red_v2(&g_acc2[dst[i]], g_gs[src[i]]);
    }
}

// ---------------------------------------------------------------------------
// 7. final: out = dinv * (acc2 + gs) + b2
__global__ void k_final(const float* __restrict__ b2, float2* __restrict__ out, int n) {
    int i = blockIdx.x * blockDim.x + threadIdx.x;
    if (i < n) {
        float di = g_dinv[i];
        float2 a = g_acc2[i];
        float2 g = g_gs[i];
        float bx = __ldg(&b2[0]);
        float by = __ldg(&b2[1]);
        out[i] = make_float2(di * (a.x + g.x) + bx,
                             di * (a.y + g.y) + by);
    }
}

// ---------------------------------------------------------------------------
extern "C" void kernel_launch(void* const* d_in, const int* in_sizes, int n_in,
                              void* d_out, int out_size) {
    const float* x  = (const float*)d_in[0];   // [N,4]
    const int*   ei = (const int*)d_in[1];     // [2,E]  int32
    const float* W1 = (const float*)d_in[2];   // [4,64]
    const float* b1 = (const float*)d_in[3];   // [64]
    const float* W2 = (const float*)d_in[4];   // [64,2]
    const float* b2 = (const float*)d_in[5];   // [2]
    float2*      out = (float2*)d_out;         // [N,2]

    const int n = in_sizes[0] / 4;
    const int e = in_sizes[1] / 2;
    const int* src = ei;
    const int* dst = ei + e;

    const int T = 256;
    const int gn  = (n + T - 1) / T;
    const int ge4 = (e / 4 + T - 1) / T;   // 4 edges/thread
    const int ge8 = (e / 8 + T - 1) / T;   // 8 edges/thread

    k_zero    <<<gn,  T>>>(n);
    k_deg     <<<ge8, T>>>(dst, e);
    k_prep    <<<gn,  T>>>((const float4*)x, n);
    k_scatter1<<<ge4, T>>>(src, dst, e);
    k_mid     <<<gn,  T>>>(W1, b1, W2, n);
    k_scatter2<<<ge4, T>>>(src, dst, e);
    k_final   <<<gn,  T>>>(b2, out, n);
}